// round 7
// baseline (speedup 1.0000x reference)
#include <cuda_runtime.h>
#include <cstdint>

#define NN 1000
#define D 128
#define STR 384          // K_att/V_att innermost stride in floats
#define SEG 250          // nodes per CTA (4 CTAs per batch)
#define CAP 128          // cached nodes per CTA (smem)
#define NWP 16           // warps per CTA
#define THREADS 512

struct SmemLayout {
    float k1c[CAP][D];   // K[128:256] slices  (layer 1)
    float v1c[CAP][D];   // V[128:256] slices  (layer 1)
    float k2c[CAP][D];   // K[256:384] slices  (layer 2)
    int   nlist[SEG + 6];
    float ss[SEG + 6];   // staged unnormalized layer-2 logits
    float qs[D];
    float mo[D];
    float m_s[NWP][32];
    float l_s[NWP][32];
    float4 a_s[NWP][32];
    float xbuf[32][6];   // cross-CTA flash partial: m,l,acc4 per lane-slot
    float x2[2];         // cross-CTA layer-2 stats
    int   cnt;
};

__device__ __forceinline__ float4 zero4() { return make_float4(0.f, 0.f, 0.f, 0.f); }

__device__ __forceinline__ uint32_t smem_u32(const void* p) {
    uint32_t a;
    asm("{ .reg .u64 t; cvta.to.shared.u64 t, %1; cvt.u32.u64 %0, t; }" : "=r"(a) : "l"(p));
    return a;
}
__device__ __forceinline__ float dsmem_ld(uint32_t laddr, uint32_t rank) {
    uint32_t ra; float v;
    asm volatile("mapa.shared::cluster.u32 %0, %1, %2;" : "=r"(ra) : "r"(laddr), "r"(rank));
    asm volatile("ld.shared::cluster.f32 %0, [%1];" : "=f"(v) : "r"(ra) : "memory");
    return v;
}
#define CLUSTER_SYNC() do { \
    asm volatile("barrier.cluster.arrive.aligned;" ::: "memory"); \
    asm volatile("barrier.cluster.wait.aligned;" ::: "memory"); } while (0)

extern __shared__ char smem_raw[];

__global__ void __cluster_dims__(4, 1, 1) __launch_bounds__(THREADS, 1)
decoder_cluster_kernel(
    const float* __restrict__ query,
    const float* __restrict__ K_att,
    const float* __restrict__ V_att,
    const int* __restrict__ mask,
    const float* __restrict__ W0_w,
    const float* __restrict__ W0_b,
    const float* __restrict__ Wq_w,
    const float* __restrict__ Wq_b,
    float* __restrict__ out)
{
    SmemLayout* S = (SmemLayout*)smem_raw;
    const int b    = blockIdx.x >> 2;
    const int rank = blockIdx.x & 3;
    const int seg0 = rank * SEG;
    const int tid  = threadIdx.x;
    const int wid  = tid >> 5;
    const int lane = tid & 31;
    const int loff = 4 * lane;

    if (tid < D) S->qs[tid] = query[(size_t)b * D + tid];

    // ---- compact unmasked nodes of this CTA's segment (warp 0) ----
    const int* mrow = mask + (size_t)b * NN;
    if (wid == 0) {
        int base = 0;
        for (int start = 0; start < SEG; start += 32) {
            int n = start + lane;
            bool keep = (n < SEG) && (mrow[seg0 + n] == 0);
            unsigned bal = __ballot_sync(0xffffffffu, keep);
            if (keep) S->nlist[base + __popc(bal & ((1u << lane) - 1u))] = seg0 + n;
            base += __popc(bal);
        }
        if (lane == 0) S->cnt = base;
    }
    __syncthreads();
    const int lcnt = S->cnt;

    const float* Kb = K_att + (size_t)b * NN * STR;
    const float* Vb = V_att + (size_t)b * NN * STR;

    // ==================== Phase A: layer 0 — full K row + V[0:256]; cache slices ====================
    {
        const float4 q4 = *(const float4*)(S->qs + loff);
        float m = -1e30f, lsum = 0.f;
        float4 acc = zero4();

        int i = wid;
        float4 ck0, ck1, ck2, cv0, cv1;
        if (i < lcnt) {
            size_t ro = (size_t)S->nlist[i] * STR;
            ck0 = *(const float4*)(Kb + ro + loff);
            ck1 = *(const float4*)(Kb + ro + D + loff);
            ck2 = *(const float4*)(Kb + ro + 2 * D + loff);
            cv0 = *(const float4*)(Vb + ro + loff);
            cv1 = *(const float4*)(Vb + ro + D + loff);
        }
        while (i < lcnt) {
            const float4 k0 = ck0, k1 = ck1, k2 = ck2, v0 = cv0, v1 = cv1;
            const int in = i + NWP;
            if (in < lcnt) {
                size_t ro = (size_t)S->nlist[in] * STR;
                ck0 = *(const float4*)(Kb + ro + loff);
                ck1 = *(const float4*)(Kb + ro + D + loff);
                ck2 = *(const float4*)(Kb + ro + 2 * D + loff);
                cv0 = *(const float4*)(Vb + ro + loff);
                cv1 = *(const float4*)(Vb + ro + D + loff);
            }
            if (i < CAP) {
                *(float4*)&S->k1c[i][loff] = k1;
                *(float4*)&S->k2c[i][loff] = k2;
                *(float4*)&S->v1c[i][loff] = v1;
            }
            float s = k0.x * q4.x + k0.y * q4.y + k0.z * q4.z + k0.w * q4.w;
            s += __shfl_xor_sync(0xffffffffu, s, 1);
            s += __shfl_xor_sync(0xffffffffu, s, 2);
            s *= 0.25f;
            const float mn = fmaxf(m, s);
            const float c = __expf(m - mn);
            const float e = __expf(s - mn);
            lsum = lsum * c + e;
            acc.x = acc.x * c + e * v0.x;
            acc.y = acc.y * c + e * v0.y;
            acc.z = acc.z * c + e * v0.z;
            acc.w = acc.w * c + e * v0.w;
            m = mn;
            i = in;
        }
        S->m_s[wid][lane] = m; S->l_s[wid][lane] = lsum; S->a_s[wid][lane] = acc;
    }
    __syncthreads();
    // local merge (16 warps) -> CTA partial in xbuf
    if (tid < 32) {
        float M = S->m_s[0][lane];
        #pragma unroll
        for (int w = 1; w < NWP; ++w) M = fmaxf(M, S->m_s[w][lane]);
        float L = 0.f, ax = 0.f, ay = 0.f, az = 0.f, aw = 0.f;
        #pragma unroll
        for (int w = 0; w < NWP; ++w) {
            const float c = __expf(S->m_s[w][lane] - M);
            L += S->l_s[w][lane] * c;
            const float4 a = S->a_s[w][lane];
            ax += a.x * c; ay += a.y * c; az += a.z * c; aw += a.w * c;
        }
        S->xbuf[lane][0] = M; S->xbuf[lane][1] = L;
        S->xbuf[lane][2] = ax; S->xbuf[lane][3] = ay;
        S->xbuf[lane][4] = az; S->xbuf[lane][5] = aw;
    }
    CLUSTER_SYNC();  // CS1: all CTA partials published
    if (tid < 32) {
        const uint32_t bx = smem_u32(&S->xbuf[lane][0]);
        float mr[4], lr[4], a0[4], a1[4], a2[4], a3[4];
        #pragma unroll
        for (int r = 0; r < 4; ++r) {
            mr[r] = dsmem_ld(bx +  0, r); lr[r] = dsmem_ld(bx +  4, r);
            a0[r] = dsmem_ld(bx +  8, r); a1[r] = dsmem_ld(bx + 12, r);
            a2[r] = dsmem_ld(bx + 16, r); a3[r] = dsmem_ld(bx + 20, r);
        }
        float M = fmaxf(fmaxf(mr[0], mr[1]), fmaxf(mr[2], mr[3]));
        float L = 0.f, ax = 0.f, ay = 0.f, az = 0.f, aw = 0.f;
        #pragma unroll
        for (int r = 0; r < 4; ++r) {
            const float c = __expf(mr[r] - M);
            L += lr[r] * c;
            ax += a0[r] * c; ay += a1[r] * c; az += a2[r] * c; aw += a3[r] * c;
        }
        const float inv = 1.0f / L;
        S->mo[loff + 0] = ax * inv; S->mo[loff + 1] = ay * inv;
        S->mo[loff + 2] = az * inv; S->mo[loff + 3] = aw * inv;
    }
    __syncthreads();
    if (tid < D) {
        const float* Wr = W0_w + tid * D;
        float a2 = W0_b[tid];
        #pragma unroll 8
        for (int d = 0; d < D; ++d) a2 = fmaf(S->mo[d], Wr[d], a2);
        S->qs[tid] = a2;
    }
    CLUSTER_SYNC();  // CS2: xbuf reads complete everywhere; q1 ready

    // ==================== Phase B: layer 1 from smem cache ====================
    {
        const float4 q4 = *(const float4*)(S->qs + loff);
        float m = -1e30f, lsum = 0.f;
        float4 acc = zero4();
        for (int i = wid; i < lcnt; i += NWP) {
            float4 k4, v4;
            if (i < CAP) {
                k4 = *(const float4*)&S->k1c[i][loff];
                v4 = *(const float4*)&S->v1c[i][loff];
            } else {
                size_t ro = (size_t)S->nlist[i] * STR;
                k4 = *(const float4*)(Kb + ro + D + loff);
                v4 = *(const float4*)(Vb + ro + D + loff);
            }
            float s = k4.x * q4.x + k4.y * q4.y + k4.z * q4.z + k4.w * q4.w;
            s += __shfl_xor_sync(0xffffffffu, s, 1);
            s += __shfl_xor_sync(0xffffffffu, s, 2);
            s *= 0.25f;
            const float mn = fmaxf(m, s);
            const float c = __expf(m - mn);
            const float e = __expf(s - mn);
            lsum = lsum * c + e;
            acc.x = acc.x * c + e * v4.x;
            acc.y = acc.y * c + e * v4.y;
            acc.z = acc.z * c + e * v4.z;
            acc.w = acc.w * c + e * v4.w;
            m = mn;
        }
        S->m_s[wid][lane] = m; S->l_s[wid][lane] = lsum; S->a_s[wid][lane] = acc;
    }
    __syncthreads();
    if (tid < 32) {
        float M = S->m_s[0][lane];
        #pragma unroll
        for (int w = 1; w < NWP; ++w) M = fmaxf(M, S->m_s[w][lane]);
        float L = 0.f, ax = 0.f, ay = 0.f, az = 0.f, aw = 0.f;
        #pragma unroll
        for (int w = 0; w < NWP; ++w) {
            const float c = __expf(S->m_s[w][lane] - M);
            L += S->l_s[w][lane] * c;
            const float4 a = S->a_s[w][lane];
            ax += a.x * c; ay += a.y * c; az += a.z * c; aw += a.w * c;
        }
        S->xbuf[lane][0] = M; S->xbuf[lane][1] = L;
        S->xbuf[lane][2] = ax; S->xbuf[lane][3] = ay;
        S->xbuf[lane][4] = az; S->xbuf[lane][5] = aw;
    }
    CLUSTER_SYNC();  // CS3
    if (tid < 32) {
        const uint32_t bx = smem_u32(&S->xbuf[lane][0]);
        float mr[4], lr[4], a0[4], a1[4], a2[4], a3[4];
        #pragma unroll
        for (int r = 0; r < 4; ++r) {
            mr[r] = dsmem_ld(bx +  0, r); lr[r] = dsmem_ld(bx +  4, r);
            a0[r] = dsmem_ld(bx +  8, r); a1[r] = dsmem_ld(bx + 12, r);
            a2[r] = dsmem_ld(bx + 16, r); a3[r] = dsmem_ld(bx + 20, r);
        }
        float M = fmaxf(fmaxf(mr[0], mr[1]), fmaxf(mr[2], mr[3]));
        float L = 0.f, ax = 0.f, ay = 0.f, az = 0.f, aw = 0.f;
        #pragma unroll
        for (int r = 0; r < 4; ++r) {
            const float c = __expf(mr[r] - M);
            L += lr[r] * c;
            ax += a0[r] * c; ay += a1[r] * c; az += a2[r] * c; aw += a3[r] * c;
        }
        const float inv = 1.0f / L;
        S->mo[loff + 0] = ax * inv; S->mo[loff + 1] = ay * inv;
        S->mo[loff + 2] = az * inv; S->mo[loff + 3] = aw * inv;
    }
    __syncthreads();
    if (tid < D) {                      // query = out1 @ W0.T + b0
        const float* Wr = W0_w + tid * D;
        float a2 = W0_b[tid];
        #pragma unroll 8
        for (int d = 0; d < D; ++d) a2 = fmaf(S->mo[d], Wr[d], a2);
        S->qs[tid] = a2;
    }
    __syncthreads();
    if (tid < D) {                      // q_final = query @ Wq.T + bq
        const float* Wr = Wq_w + tid * D;
        float a2 = Wq_b[tid];
        #pragma unroll 8
        for (int d = 0; d < D; ++d) a2 = fmaf(S->qs[d], Wr[d], a2);
        S->mo[tid] = a2;
    }
    __syncthreads();

    // ==================== Phase C: layer 2 (1 head, clip 10) from smem cache ====================
    {
        const float4 q4 = *(const float4*)(S->mo + loff);
        float m = -1e30f, lsum = 0.f;
        for (int i = wid; i < lcnt; i += NWP) {
            const int node = S->nlist[i];
            float4 k4;
            if (i < CAP) k4 = *(const float4*)&S->k2c[i][loff];
            else         k4 = *(const float4*)(Kb + (size_t)node * STR + 2 * D + loff);

            float s = k4.x * q4.x + k4.y * q4.y + k4.z * q4.z + k4.w * q4.w;
            #pragma unroll
            for (int d = 1; d < 32; d <<= 1)
                s += __shfl_xor_sync(0xffffffffu, s, d);
            s *= 0.08838834764831845f;
            s = 10.0f * (1.0f - __fdividef(2.0f, __expf(2.0f * s) + 1.0f));  // 10*tanh

            if (lane == 0) S->ss[node - seg0] = s;
            const float mn = fmaxf(m, s);
            lsum = lsum * __expf(m - mn) + __expf(s - mn);
            m = mn;
        }
        if (lane == 0) { S->m_s[wid][0] = m; S->l_s[wid][0] = lsum; }
    }
    __syncthreads();
    if (tid == 0) {
        float M = S->m_s[0][0];
        #pragma unroll
        for (int w = 1; w < NWP; ++w) M = fmaxf(M, S->m_s[w][0]);
        float L = 0.f;
        #pragma unroll
        for (int w = 0; w < NWP; ++w) L += S->l_s[w][0] * __expf(S->m_s[w][0] - M);
        S->x2[0] = M; S->x2[1] = L;
    }
    CLUSTER_SYNC();  // CS4
    if (tid == 0) {
        const uint32_t bx = smem_u32(&S->x2[0]);
        float mr[4], lr[4];
        #pragma unroll
        for (int r = 0; r < 4; ++r) { mr[r] = dsmem_ld(bx, r); lr[r] = dsmem_ld(bx + 4, r); }
        float M = fmaxf(fmaxf(mr[0], mr[1]), fmaxf(mr[2], mr[3]));
        float L = 0.f;
        #pragma unroll
        for (int r = 0; r < 4; ++r) L += lr[r] * __expf(mr[r] - M);
        S->qs[0] = M; S->qs[1] = 1.0f / L;
    }
    CLUSTER_SYNC();  // CS5: x2 reads done cluster-wide; M/Li ready

    {
        const float M = S->qs[0], Li = S->qs[1];
        float* orow = out + (size_t)b * NN + seg0;
        for (int n0 = tid; n0 < SEG; n0 += THREADS) {
            float v = 0.0f;
            if (mrow[seg0 + n0] == 0) v = __expf(S->ss[n0] - M) * Li;
            orow[n0] = v;
        }
    }
}

extern "C" void kernel_launch(void* const* d_in, const int* in_sizes, int n_in,
                              void* d_out, int out_size) {
    const float* query = (const float*)d_in[0];
    const float* K_att = (const float*)d_in[1];
    const float* V_att = (const float*)d_in[2];
    const int*   mask  = (const int*)d_in[3];
    const float* W0_w  = (const float*)d_in[4];
    const float* W0_b  = (const float*)d_in[5];
    const float* Wq_w  = (const float*)d_in[6];
    const float* Wq_b  = (const float*)d_in[7];
    float* out = (float*)d_out;

    const int smem_bytes = (int)sizeof(SmemLayout);
    cudaFuncSetAttribute(decoder_cluster_kernel,
                         cudaFuncAttributeMaxDynamicSharedMemorySize, smem_bytes);
    decoder_cluster_kernel<<<512 * 4, THREADS, smem_bytes>>>(
        query, K_att, V_att, mask, W0_w, W0_b, Wq_w, Wq_b, out);
}

// round 8
// speedup vs baseline: 3.1420x; 3.1420x over previous
#include <cuda_runtime.h>
#include <cuda_pipeline.h>
#include <cstdint>

#define NN 1000
#define D 128
#define STR 384      // K_att/V_att innermost stride in floats (3 * 128)
#define NW 8         // warps per CTA
#define CH 3         // adjacent nodes per chunk (row-locality unit)
#define DEPTH 2      // double buffer

__device__ __forceinline__ float4 zero4() { return make_float4(0.f, 0.f, 0.f, 0.f); }

// One CTA per batch, 8 warps, occupancy 4 (32 warps/SM, single wave).
// Warp w consumes chunks w, w+8, ... ; a chunk = 3 ADJACENT compact nodes,
// whose K/V slices are cp.async'd back-to-back => DRAM row hits instead of
// repeated activates. Ring: ring[w][buf][node][0:128]=K, [128:256]=V.

__global__ __launch_bounds__(256, 4)
void decoder_fused_kernel(
    const float* __restrict__ query,
    const float* __restrict__ K_att,
    const float* __restrict__ V_att,
    const int* __restrict__ mask,          // bool serialized as int32
    const float* __restrict__ W0_w,
    const float* __restrict__ W0_b,
    const float* __restrict__ Wq_w,
    const float* __restrict__ Wq_b,
    float* __restrict__ out)
{
    __shared__ __align__(16) float ring[NW * DEPTH * CH * 256];  // 48 KB
    __shared__ int nlist[NN];
    __shared__ __align__(16) float qs[D];
    __shared__ __align__(16) float mo[D];
    __shared__ float M2s, L2s;
    __shared__ int cnt_s;

    // merge scratch aliased onto ring (dead between layer loops)
    float*  m_s = ring;              // [NW][32]
    float*  l_s = ring + 256;        // [NW][32]
    float4* a_s = (float4*)(ring + 512);  // [NW][32]

    const int b = blockIdx.x;
    const int tid = threadIdx.x;
    const int wid = tid >> 5;
    const int lane = tid & 31;
    const int loff = 4 * lane;
    const float NEG = __int_as_float(0xff800000);  // -inf

    if (tid < D) qs[tid] = query[(size_t)b * D + tid];

    // ---- Compact unmasked node list (warp 0) ----
    const int* mrow = mask + (size_t)b * NN;
    if (wid == 0) {
        int base = 0;
        for (int start = 0; start < NN; start += 32) {
            int n = start + lane;
            bool keep = (n < NN) && (mrow[n] == 0);
            unsigned bal = __ballot_sync(0xffffffffu, keep);
            if (keep) nlist[base + __popc(bal & ((1u << lane) - 1u))] = n;
            base += __popc(bal);
        }
        if (lane == 0) cnt_s = base;
    }
    __syncthreads();
    const int cnt = cnt_s;
    const int nch = (cnt + CH - 1) / CH;

    const float* Kb = K_att + (size_t)b * NN * STR;
    const float* Vb = V_att + (size_t)b * NN * STR;
    float* rw = ring + wid * (DEPTH * CH * 256);

    // ==================== Layers 0 and 1 ====================
    for (int l = 0; l < 2; ++l) {
        const int cbase = l * D + loff;

        // prologue: fill both buffers (chunks w, w+NW)
        #pragma unroll
        for (int d = 0; d < DEPTH; ++d) {
            const int c = wid + d * NW;
            float* buf = rw + d * (CH * 256);
            if (c < nch) {
                #pragma unroll
                for (int j = 0; j < CH; ++j) {
                    int i = c * CH + j;
                    int node = nlist[i < cnt ? i : 0];
                    size_t o = (size_t)node * STR + cbase;
                    __pipeline_memcpy_async(buf + j * 256 + loff, Kb + o, 16);
                    __pipeline_memcpy_async(buf + j * 256 + 128 + loff, Vb + o, 16);
                }
            }
            __pipeline_commit();
        }

        const float4 q4 = *(const float4*)(qs + loff);
        float m = -1e30f, lsum = 0.0f;
        float4 acc = zero4();

        int it = 0;
        for (int c = wid; c < nch; c += NW, ++it) {
            __pipeline_wait_prior(1);
            float* buf = rw + (it & 1) * (CH * 256);

            #pragma unroll
            for (int j = 0; j < CH; ++j) {
                const float4 k4 = *(const float4*)(buf + j * 256 + loff);
                const float4 v4 = *(const float4*)(buf + j * 256 + 128 + loff);
                float s = k4.x * q4.x + k4.y * q4.y + k4.z * q4.z + k4.w * q4.w;
                s += __shfl_xor_sync(0xffffffffu, s, 1);
                s += __shfl_xor_sync(0xffffffffu, s, 2);
                s = (c * CH + j < cnt) ? s * 0.25f : NEG;  // 1/sqrt(16)

                const float mn = fmaxf(m, s);
                const float cc = __expf(m - mn);
                const float e = __expf(s - mn);     // 0 for invalid slots
                lsum = lsum * cc + e;
                acc.x = acc.x * cc + e * v4.x;
                acc.y = acc.y * cc + e * v4.y;
                acc.z = acc.z * cc + e * v4.z;
                acc.w = acc.w * cc + e * v4.w;
                m = mn;
            }

            // refill this buffer with chunk c + 2*NW
            const int cn = c + 2 * NW;
            if (cn < nch) {
                #pragma unroll
                for (int j = 0; j < CH; ++j) {
                    int i = cn * CH + j;
                    int node = nlist[i < cnt ? i : 0];
                    size_t o = (size_t)node * STR + cbase;
                    __pipeline_memcpy_async(buf + j * 256 + loff, Kb + o, 16);
                    __pipeline_memcpy_async(buf + j * 256 + 128 + loff, Vb + o, 16);
                }
            }
            __pipeline_commit();
        }
        __pipeline_wait_prior(0);
        __syncthreads();   // ring now dead -> reuse as merge scratch

        m_s[wid * 32 + lane] = m;
        l_s[wid * 32 + lane] = lsum;
        a_s[wid * 32 + lane] = acc;
        __syncthreads();

        if (tid < 32) {
            float M = m_s[lane];
            #pragma unroll
            for (int w = 1; w < NW; ++w) M = fmaxf(M, m_s[w * 32 + lane]);
            float L = 0.f, ax = 0.f, ay = 0.f, az = 0.f, aw = 0.f;
            #pragma unroll
            for (int w = 0; w < NW; ++w) {
                const float cc = __expf(m_s[w * 32 + lane] - M);
                L += l_s[w * 32 + lane] * cc;
                const float4 a = a_s[w * 32 + lane];
                ax += a.x * cc; ay += a.y * cc; az += a.z * cc; aw += a.w * cc;
            }
            const float inv = 1.0f / L;
            mo[4 * lane + 0] = ax * inv;
            mo[4 * lane + 1] = ay * inv;
            mo[4 * lane + 2] = az * inv;
            mo[4 * lane + 3] = aw * inv;
        }
        __syncthreads();

        if (tid < D) {   // query = mha_out @ W0_w.T + W0_b
            const float* Wr = W0_w + tid * D;
            float a2 = W0_b[tid];
            #pragma unroll 8
            for (int d = 0; d < D; ++d) a2 = fmaf(mo[d], Wr[d], a2);
            qs[tid] = a2;
        }
        __syncthreads();
    }

    // ==================== Layer 2: q_final = q @ Wq.T + b; 1-head, clip=10 ====================
    if (tid < D) {
        const float* Wr = Wq_w + tid * D;
        float a2 = Wq_b[tid];
        #pragma unroll 8
        for (int d = 0; d < D; ++d) a2 = fmaf(qs[d], Wr[d], a2);
        mo[tid] = a2;
    }
    __syncthreads();

    {
        const int cbase = 2 * D + loff;
        const float4 q4 = *(const float4*)(mo + loff);
        float* orow = out + (size_t)b * NN;

        // K-only ring: slot = ring[w][buf][j][0:128]
        #pragma unroll
        for (int d = 0; d < DEPTH; ++d) {
            const int c = wid + d * NW;
            float* buf = rw + d * (CH * 256);
            if (c < nch) {
                #pragma unroll
                for (int j = 0; j < CH; ++j) {
                    int i = c * CH + j;
                    int node = nlist[i < cnt ? i : 0];
                    __pipeline_memcpy_async(buf + j * 256 + loff,
                                            Kb + (size_t)node * STR + cbase, 16);
                }
            }
            __pipeline_commit();
        }

        float m = -1e30f, lsum = 0.0f;
        int it = 0;
        for (int c = wid; c < nch; c += NW, ++it) {
            __pipeline_wait_prior(1);
            float* buf = rw + (it & 1) * (CH * 256);

            #pragma unroll
            for (int j = 0; j < CH; ++j) {
                const int i = c * CH + j;
                const float4 k4 = *(const float4*)(buf + j * 256 + loff);
                float s = k4.x * q4.x + k4.y * q4.y + k4.z * q4.z + k4.w * q4.w;
                #pragma unroll
                for (int d = 1; d < 32; d <<= 1)
                    s += __shfl_xor_sync(0xffffffffu, s, d);
                s *= 0.08838834764831845f;  // 1/sqrt(128)
                s = 10.0f * (1.0f - __fdividef(2.0f, __expf(2.0f * s) + 1.0f));  // 10*tanh
                if (i < cnt) {
                    if (lane == 0) orow[nlist[i]] = s;
                } else s = NEG;
                const float mn = fmaxf(m, s);
                lsum = lsum * __expf(m - mn) + __expf(s - mn);
                m = mn;
            }

            const int cn = c + 2 * NW;
            if (cn < nch) {
                #pragma unroll
                for (int j = 0; j < CH; ++j) {
                    int i = cn * CH + j;
                    int node = nlist[i < cnt ? i : 0];
                    __pipeline_memcpy_async(buf + j * 256 + loff,
                                            Kb + (size_t)node * STR + cbase, 16);
                }
            }
            __pipeline_commit();
        }
        __pipeline_wait_prior(0);
        __syncthreads();

        if (lane == 0) { m_s[wid * 32] = m; l_s[wid * 32] = lsum; }
        __syncthreads();
        if (tid == 0) {
            float M = m_s[0];
            #pragma unroll
            for (int w = 1; w < NW; ++w) M = fmaxf(M, m_s[w * 32]);
            float L = 0.f;
            #pragma unroll
            for (int w = 0; w < NW; ++w) L += l_s[w * 32] * __expf(m_s[w * 32] - M);
            M2s = M;
            L2s = 1.0f / L;
        }
        __syncthreads();

        const float M = M2s, Li = L2s;
        for (int n = tid; n < NN; n += 256) {
            float v = 0.0f;
            if (mrow[n] == 0) v = __expf(orow[n] - M) * Li;
            orow[n] = v;
        }
    }
}

extern "C" void kernel_launch(void* const* d_in, const int* in_sizes, int n_in,
                              void* d_out, int out_size) {
    const float* query = (const float*)d_in[0];
    const float* K_att = (const float*)d_in[1];
    const float* V_att = (const float*)d_in[2];
    const int*   mask  = (const int*)d_in[3];
    const float* W0_w  = (const float*)d_in[4];
    const float* W0_b  = (const float*)d_in[5];
    const float* Wq_w  = (const float*)d_in[6];
    const float* Wq_b  = (const float*)d_in[7];
    float* out = (float*)d_out;

    decoder_fused_kernel<<<512, 256>>>(query, K_att, V_att, mask,
                                       W0_w, W0_b, Wq_w, Wq_b, out);
}